// round 8
// baseline (speedup 1.0000x reference)
#include <cuda_runtime.h>
#include <cstdint>

// GCN_79568564126323: 2-layer GCN, N=200000, E=3200000, dims 4 -> 16 -> 1.
//
// Aggregate-before-matmul, normalization factored out of edge loops:
//   agg[d] = dinv[d]*(sum_{s->d} xs[s] + xs[d]),  xs = x*dinv
//   z = relu(agg@W1+b1)@W2, zs = z*dinv
//   out[d] = dinv[d]*(sum_{s->d} zs[s] + zs[d]) + b2
//
// Edge passes are at the LTS sector roofline (~8 sector-equiv/edge total);
// R8 attacks the node kernels: k_dense prefetches its global operands before
// the smem stage + barrier (hides L2 latency), 128-thread blocks.

#define N_MAX 200000

__device__ int    g_cnt [N_MAX];   // zero-init; re-zeroed by k_prep each call
__device__ float  g_dinv[N_MAX];
__device__ float4 g_xs  [N_MAX];   // x * dinv
__device__ float4 g_agg [N_MAX];   // f32 aggregate (seeded with self-loop xs)
__device__ float  g_zs  [N_MAX];   // z * dinv

// ---------------------------------------------------------------- helpers

__device__ __forceinline__ void red_v4(float4* p, float4 v) {
    unsigned long long gp = (unsigned long long)__cvta_generic_to_global(p);
    asm volatile("red.global.add.v4.f32 [%0], {%1, %2, %3, %4};"
                 :: "l"(gp), "f"(v.x), "f"(v.y), "f"(v.z), "f"(v.w)
                 : "memory");
}

// ---------------------------------------------------------------- kernels

__global__ void k_count_deg(const int* __restrict__ dst, int e) {
    int i  = blockIdx.x * blockDim.x + threadIdx.x;
    int e4 = e >> 2;
    if (i < e4) {
        int4 d = ((const int4*)dst)[i];
        atomicAdd(&g_cnt[d.x], 1);
        atomicAdd(&g_cnt[d.y], 1);
        atomicAdd(&g_cnt[d.z], 1);
        atomicAdd(&g_cnt[d.w], 1);
    } else {
        int t = (e4 << 2) + (i - e4);      // tail edges
        if (t < e) atomicAdd(&g_cnt[dst[t]], 1);
    }
}

// dinv = rsqrt(cnt+1); xs = x*dinv; agg seeded with self-loop xs; cnt re-zeroed
__global__ void k_prep(const float4* __restrict__ x, int n) {
    int i = blockIdx.x * blockDim.x + threadIdx.x;
    if (i >= n) return;
    int   c  = g_cnt[i];
    float4 xv = x[i];                           // overlap the two loads
    float di = rsqrtf((float)(c + 1));          // +1 = self loop
    g_cnt[i]  = 0;                              // ready for next replay
    g_dinv[i] = di;
    float4 xs = make_float4(xv.x * di, xv.y * di, xv.z * di, xv.w * di);
    g_xs[i]  = xs;
    g_agg[i] = xs;                              // self-loop contribution
}

// layer-1 edge scatter: agg[d] += xs[s]   (4 edges per thread)
__global__ void k_scatter1(const int* __restrict__ src,
                           const int* __restrict__ dst, int e) {
    int i  = blockIdx.x * blockDim.x + threadIdx.x;
    int e4 = e >> 2;
    if (i < e4) {
        int4 s = ((const int4*)src)[i];
        int4 d = ((const int4*)dst)[i];
        float4 v0 = __ldg(&g_xs[s.x]);
        float4 v1 = __ldg(&g_xs[s.y]);
        float4 v2 = __ldg(&g_xs[s.z]);
        float4 v3 = __ldg(&g_xs[s.w]);
        red_v4(&g_agg[d.x], v0);
        red_v4(&g_agg[d.y], v1);
        red_v4(&g_agg[d.z], v2);
        red_v4(&g_agg[d.w], v3);
    } else {
        int t = (e4 << 2) + (i - e4);
        if (t < e) red_v4(&g_agg[dst[t]], __ldg(&g_xs[src[t]]));
    }
}

// per-node dense, 1 node/thread; global operands prefetched BEFORE the
// smem stage + barrier so LDG latency overlaps them.
__global__ void __launch_bounds__(128, 12)
k_dense(const float* __restrict__ W1,
        const float* __restrict__ b1,
        const float* __restrict__ W2,
        float* __restrict__ out, int n) {
    __shared__ float sW1[64], sb1[16], sW2[16];
    int t = threadIdx.x;
    int i = blockIdx.x * blockDim.x + t;

    // prefetch (issue LDGs first; consumed after the barrier)
    float  di = 0.0f;
    float4 a  = make_float4(0.f, 0.f, 0.f, 0.f);
    if (i < n) {
        di = g_dinv[i];
        a  = g_agg[i];
    }

    if (t < 64) sW1[t] = W1[t];
    if (t < 16) { sb1[t] = b1[t]; sW2[t] = W2[t]; }
    __syncthreads();

    if (i >= n) return;
    float ax = a.x * di, ay = a.y * di, az = a.z * di, aw = a.w * di;
    float z = 0.0f;
#pragma unroll
    for (int j = 0; j < 16; j++) {
        float h = sb1[j];
        h = fmaf(ax, sW1[ 0 + j], h);
        h = fmaf(ay, sW1[16 + j], h);
        h = fmaf(az, sW1[32 + j], h);
        h = fmaf(aw, sW1[48 + j], h);
        h = fmaxf(h, 0.0f);
        z = fmaf(h, sW2[j], z);
    }
    float zs = z * di;
    g_zs[i] = zs;
    out[i]  = zs;                               // self-loop contribution
}

// layer-2 edge scatter: out[d] += zs[s]   (4 edges per thread)
__global__ void k_scatter2(const int* __restrict__ src,
                           const int* __restrict__ dst,
                           float* __restrict__ out, int e) {
    int i  = blockIdx.x * blockDim.x + threadIdx.x;
    int e4 = e >> 2;
    if (i < e4) {
        int4 s = ((const int4*)src)[i];
        int4 d = ((const int4*)dst)[i];
        float v0 = __ldg(&g_zs[s.x]);
        float v1 = __ldg(&g_zs[s.y]);
        float v2 = __ldg(&g_zs[s.z]);
        float v3 = __ldg(&g_zs[s.w]);
        atomicAdd(&out[d.x], v0);
        atomicAdd(&out[d.y], v1);
        atomicAdd(&out[d.z], v2);
        atomicAdd(&out[d.w], v3);
    } else {
        int t = (e4 << 2) + (i - e4);
        if (t < e) atomicAdd(&out[dst[t]], __ldg(&g_zs[src[t]]));
    }
}

// final per-node scale: out = out*dinv + b2   (4 nodes per thread)
__global__ void k_final(const float* __restrict__ b2,
                        float* __restrict__ out, int n) {
    int i  = blockIdx.x * blockDim.x + threadIdx.x;
    int n4 = n >> 2;
    float b = b2[0];
    if (i < n4) {
        float4 o = ((const float4*)out)[i];
        float4 d = ((const float4*)g_dinv)[i];
        o.x = fmaf(o.x, d.x, b);
        o.y = fmaf(o.y, d.y, b);
        o.z = fmaf(o.z, d.z, b);
        o.w = fmaf(o.w, d.w, b);
        ((float4*)out)[i] = o;
    } else {
        int t = (n4 << 2) + (i - n4);           // tail nodes
        if (t < n) out[t] = fmaf(out[t], g_dinv[t], b);
    }
}

// ---------------------------------------------------------------- launch

extern "C" void kernel_launch(void* const* d_in, const int* in_sizes, int n_in,
                              void* d_out, int out_size) {
    const float* x   = (const float*)d_in[0];   // [N,4] f32
    const int*   ei  = (const int*)d_in[1];     // [2,E] int32
    const float* W1  = (const float*)d_in[2];   // [4,16]
    const float* b1  = (const float*)d_in[3];   // [16]
    const float* W2  = (const float*)d_in[4];   // [16,1]
    const float* b2  = (const float*)d_in[5];   // [1]
    float*       out = (float*)d_out;           // [N,1]

    const int n = in_sizes[0] / 4;
    const int e = in_sizes[1] / 2;
    const int* src = ei;
    const int* dst = ei + e;

    const int T  = 256;
    const int e4 = e >> 2;
    const int et = e4 + (e & 3);
    const int ge = (et + T - 1) / T;
    const int n4 = n >> 2;
    const int nt = n4 + (n & 3);
    const int gf = (nt + T - 1) / T;

    const int Tn = 128;                          // node kernels
    const int gp = (n + Tn - 1) / Tn;

    k_count_deg<<<ge, T>>>(dst, e);
    k_prep     <<<gp, Tn>>>((const float4*)x, n);
    k_scatter1 <<<ge, T>>>(src, dst, e);
    k_dense    <<<gp, Tn>>>(W1, b1, W2, out, n);
    k_scatter2 <<<ge, T>>>(src, dst, out, e);
    k_final    <<<gf, T>>>(b2, out, n);
}

// round 9
// speedup vs baseline: 1.0217x; 1.0217x over previous
#include <cuda_runtime.h>
#include <cstdint>

// GCN_79568564126323: 2-layer GCN, N=200000, E=3200000, dims 4 -> 16 -> 1.
//
// Aggregate-before-matmul, normalization factored out of edge loops:
//   agg[d] = dinv[d]*(sum_{s->d} xs[s] + xs[d]),  xs = x*dinv
//   z = relu(agg@W1+b1)@W2, zs = z*dinv
//   out[d] = dinv[d]*(sum_{s->d} zs[s] + zs[d]) + b2
//
// Edge passes are at the LTS sector roofline. R9: node kernels were
// LSU-issue bound (scalar LDG/STG per node); now 4 CONTIGUOUS nodes per
// thread so all node-side traffic is LDG.128/STG.128.

#define N_MAX 200000

__device__ int    g_cnt [N_MAX];   // zero-init; re-zeroed by k_prep each call
__device__ float  g_dinv[N_MAX];
__device__ float4 g_xs  [N_MAX];   // x * dinv
__device__ float4 g_agg [N_MAX];   // f32 aggregate (seeded with self-loop xs)
__device__ float  g_zs  [N_MAX];   // z * dinv

// ---------------------------------------------------------------- helpers

__device__ __forceinline__ void red_v4(float4* p, float4 v) {
    unsigned long long gp = (unsigned long long)__cvta_generic_to_global(p);
    asm volatile("red.global.add.v4.f32 [%0], {%1, %2, %3, %4};"
                 :: "l"(gp), "f"(v.x), "f"(v.y), "f"(v.z), "f"(v.w)
                 : "memory");
}

// ---------------------------------------------------------------- kernels

__global__ void k_count_deg(const int* __restrict__ dst, int e) {
    int i  = blockIdx.x * blockDim.x + threadIdx.x;
    int e4 = e >> 2;
    if (i < e4) {
        int4 d = ((const int4*)dst)[i];
        atomicAdd(&g_cnt[d.x], 1);
        atomicAdd(&g_cnt[d.y], 1);
        atomicAdd(&g_cnt[d.z], 1);
        atomicAdd(&g_cnt[d.w], 1);
    } else {
        int t = (e4 << 2) + (i - e4);      // tail edges
        if (t < e) atomicAdd(&g_cnt[dst[t]], 1);
    }
}

// 4 contiguous nodes/thread: dinv = rsqrt(cnt+1); xs = x*dinv;
// agg seeded with self-loop xs; cnt re-zeroed. All accesses vectorized.
__global__ void k_prep(const float4* __restrict__ x, int n) {
    int i  = blockIdx.x * blockDim.x + threadIdx.x;   // quad index
    int n4 = n >> 2;
    if (i < n4) {
        int4 c = ((const int4*)g_cnt)[i];
        float4 x0 = x[4 * i + 0];
        float4 x1 = x[4 * i + 1];
        float4 x2 = x[4 * i + 2];
        float4 x3 = x[4 * i + 3];
        float4 di;
        di.x = rsqrtf((float)(c.x + 1));
        di.y = rsqrtf((float)(c.y + 1));
        di.z = rsqrtf((float)(c.z + 1));
        di.w = rsqrtf((float)(c.w + 1));
        ((int4*)g_cnt)[i] = make_int4(0, 0, 0, 0);
        ((float4*)g_dinv)[i] = di;
        float4 s0 = make_float4(x0.x*di.x, x0.y*di.x, x0.z*di.x, x0.w*di.x);
        float4 s1 = make_float4(x1.x*di.y, x1.y*di.y, x1.z*di.y, x1.w*di.y);
        float4 s2 = make_float4(x2.x*di.z, x2.y*di.z, x2.z*di.z, x2.w*di.z);
        float4 s3 = make_float4(x3.x*di.w, x3.y*di.w, x3.z*di.w, x3.w*di.w);
        g_xs[4*i+0] = s0;  g_agg[4*i+0] = s0;
        g_xs[4*i+1] = s1;  g_agg[4*i+1] = s1;
        g_xs[4*i+2] = s2;  g_agg[4*i+2] = s2;
        g_xs[4*i+3] = s3;  g_agg[4*i+3] = s3;
    } else {
        int t = (n4 << 2) + (i - n4);                 // tail nodes
        if (t < n) {
            float di = rsqrtf((float)(g_cnt[t] + 1));
            g_cnt[t]  = 0;
            g_dinv[t] = di;
            float4 xv = x[t];
            float4 xs = make_float4(xv.x*di, xv.y*di, xv.z*di, xv.w*di);
            g_xs[t]  = xs;
            g_agg[t] = xs;
        }
    }
}

// layer-1 edge scatter: agg[d] += xs[s]   (4 edges per thread)
__global__ void k_scatter1(const int* __restrict__ src,
                           const int* __restrict__ dst, int e) {
    int i  = blockIdx.x * blockDim.x + threadIdx.x;
    int e4 = e >> 2;
    if (i < e4) {
        int4 s = ((const int4*)src)[i];
        int4 d = ((const int4*)dst)[i];
        float4 v0 = __ldg(&g_xs[s.x]);
        float4 v1 = __ldg(&g_xs[s.y]);
        float4 v2 = __ldg(&g_xs[s.z]);
        float4 v3 = __ldg(&g_xs[s.w]);
        red_v4(&g_agg[d.x], v0);
        red_v4(&g_agg[d.y], v1);
        red_v4(&g_agg[d.z], v2);
        red_v4(&g_agg[d.w], v3);
    } else {
        int t = (e4 << 2) + (i - e4);
        if (t < e) red_v4(&g_agg[dst[t]], __ldg(&g_xs[src[t]]));
    }
}

// per-node dense, 4 contiguous nodes/thread, weights in smem, all I/O v128.
__global__ void k_dense(const float* __restrict__ W1,
                        const float* __restrict__ b1,
                        const float* __restrict__ W2,
                        float* __restrict__ out, int n) {
    __shared__ float sW1[64], sb1[16], sW2[16];
    int t = threadIdx.x;
    int i = blockIdx.x * blockDim.x + t;              // quad index
    int n4 = n >> 2;

    // prefetch global operands before smem stage + barrier
    float4 di = make_float4(0.f, 0.f, 0.f, 0.f);
    float4 a[4];
    bool vec = (i < n4);
    if (vec) {
        di   = ((const float4*)g_dinv)[i];
        a[0] = g_agg[4 * i + 0];
        a[1] = g_agg[4 * i + 1];
        a[2] = g_agg[4 * i + 2];
        a[3] = g_agg[4 * i + 3];
    }

    if (t < 64) sW1[t] = W1[t];
    if (t < 16) { sb1[t] = b1[t]; sW2[t] = W2[t]; }
    __syncthreads();

    if (vec) {
        float dd[4] = {di.x, di.y, di.z, di.w};
        float z[4]  = {0.f, 0.f, 0.f, 0.f};
        float ax[4], ay[4], az[4], aw[4];
#pragma unroll
        for (int m = 0; m < 4; m++) {
            ax[m] = a[m].x * dd[m]; ay[m] = a[m].y * dd[m];
            az[m] = a[m].z * dd[m]; aw[m] = a[m].w * dd[m];
        }
#pragma unroll
        for (int j = 0; j < 16; j++) {
            float w0 = sW1[j], w1 = sW1[16 + j];
            float w2 = sW1[32 + j], w3 = sW1[48 + j];
            float bb = sb1[j], wz = sW2[j];
#pragma unroll
            for (int m = 0; m < 4; m++) {
                float h = bb;
                h = fmaf(ax[m], w0, h);
                h = fmaf(ay[m], w1, h);
                h = fmaf(az[m], w2, h);
                h = fmaf(aw[m], w3, h);
                h = fmaxf(h, 0.0f);
                z[m] = fmaf(h, wz, z[m]);
            }
        }
        float4 zs = make_float4(z[0]*dd[0], z[1]*dd[1], z[2]*dd[2], z[3]*dd[3]);
        ((float4*)g_zs)[i] = zs;
        ((float4*)out)[i]  = zs;                      // self-loop contribution
    } else {
        int q = (n4 << 2) + (i - n4);                 // tail nodes
        if (q < n) {
            float  d = g_dinv[q];
            float4 av = g_agg[q];
            float ax = av.x*d, ay = av.y*d, az = av.z*d, aw = av.w*d;
            float z = 0.0f;
#pragma unroll
            for (int j = 0; j < 16; j++) {
                float h = sb1[j];
                h = fmaf(ax, sW1[ 0 + j], h);
                h = fmaf(ay, sW1[16 + j], h);
                h = fmaf(az, sW1[32 + j], h);
                h = fmaf(aw, sW1[48 + j], h);
                h = fmaxf(h, 0.0f);
                z = fmaf(h, sW2[j], z);
            }
            float zs = z * d;
            g_zs[q] = zs;
            out[q]  = zs;
        }
    }
}

// layer-2 edge scatter: out[d] += zs[s]   (4 edges per thread)
__global__ void k_scatter2(const int* __restrict__ src,
                           const int* __restrict__ dst,
                           float* __restrict__ out, int e) {
    int i  = blockIdx.x * blockDim.x + threadIdx.x;
    int e4 = e >> 2;
    if (i < e4) {
        int4 s = ((const int4*)src)[i];
        int4 d = ((const int4*)dst)[i];
        float v0 = __ldg(&g_zs[s.x]);
        float v1 = __ldg(&g_zs[s.y]);
        float v2 = __ldg(&g_zs[s.z]);
        float v3 = __ldg(&g_zs[s.w]);
        atomicAdd(&out[d.x], v0);
        atomicAdd(&out[d.y], v1);
        atomicAdd(&out[d.z], v2);
        atomicAdd(&out[d.w], v3);
    } else {
        int t = (e4 << 2) + (i - e4);
        if (t < e) atomicAdd(&out[dst[t]], __ldg(&g_zs[src[t]]));
    }
}

// final per-node scale: out = out*dinv + b2   (4 nodes per thread)
__global__ void k_final(const float* __restrict__ b2,
                        float* __restrict__ out, int n) {
    int i  = blockIdx.x * blockDim.x + threadIdx.x;
    int n4 = n >> 2;
    float b = b2[0];
    if (i < n4) {
        float4 o = ((const float4*)out)[i];
        float4 d = ((const float4*)g_dinv)[i];
        o.x = fmaf(o.x, d.x, b);
        o.y = fmaf(o.y, d.y, b);
        o.z = fmaf(o.z, d.z, b);
        o.w = fmaf(o.w, d.w, b);
        ((float4*)out)[i] = o;
    } else {
        int t = (n4 << 2) + (i - n4);                 // tail nodes
        if (t < n) out[t] = fmaf(out[t], g_dinv[t], b);
    }
}

// ---------------------------------------------------------------- launch

extern "C" void kernel_launch(void* const* d_in, const int* in_sizes, int n_in,
                              void* d_out, int out_size) {
    const float* x   = (const float*)d_in[0];   // [N,4] f32
    const int*   ei  = (const int*)d_in[1];     // [2,E] int32
    const float* W1  = (const float*)d_in[2];   // [4,16]
    const float* b1  = (const float*)d_in[3];   // [16]
    const float* W2  = (const float*)d_in[4];   // [16,1]
    const float* b2  = (const float*)d_in[5];   // [1]
    float*       out = (float*)d_out;           // [N,1]

    const int n = in_sizes[0] / 4;
    const int e = in_sizes[1] / 2;
    const int* src = ei;
    const int* dst = ei + e;

    const int T  = 256;
    const int e4 = e >> 2;
    const int et = e4 + (e & 3);
    const int ge = (et + T - 1) / T;
    const int n4 = n >> 2;
    const int nt = n4 + (n & 3);                 // quad threads + tail threads
    const int gq = (nt + T - 1) / T;

    k_count_deg<<<ge, T>>>(dst, e);
    k_prep     <<<gq, T>>>((const float4*)x, n);
    k_scatter1 <<<ge, T>>>(src, dst, e);
    k_dense    <<<gq, T>>>(W1, b1, W2, out, n);
    k_scatter2 <<<ge, T>>>(src, dst, out, e);
    k_final    <<<gq, T>>>(b2, out, n);
}